// round 16
// baseline (speedup 1.0000x reference)
#include <cuda_runtime.h>
#include <math.h>
#include <stdint.h>

// Problem constants
#define Bb 32
#define Tt 64
#define Ee 64
#define Uu 32
#define D0 300
#define D1 100
#define Ss 9
#define CELL 64
#define Cc 6
#define ROWS (Bb*Tt)      // 2048
#define G4E (4*Ee)        // 256
#define KC 100            // uniform K-chunk
#define KP 104            // K padded to multiple of 8
#define KSTR 105          // smem row stride (elements)
#define EPW 16            // epilogue rows (warps) per block

// Device scratch
__device__ float g_xp0a[ROWS * G4E];
__device__ float g_xp0b[ROWS * G4E];
__device__ float g_xp0c[ROWS * G4E];
__device__ float g_xp1 [ROWS * G4E];
__device__ float g_h0[ROWS * Ee];
__device__ float g_h1[ROWS * Ee];
__device__ float2 g_krki[Ee * Uu];   // [e][u] -> (kr, ki), normalized
__device__ float2 g_ph2[Ss * Ee];    // [s][e] -> (cos, sin)

typedef unsigned long long u64;

// ---------------------------------------------------------------------------
__device__ __forceinline__ float tanha(float x) {
    float y;
    asm("tanh.approx.f32 %0, %1;" : "=f"(y) : "f"(x));
    return y;
}
__device__ __forceinline__ float fsig(float x) {
    return fmaf(tanha(0.5f * x), 0.5f, 0.5f);
}
__device__ __forceinline__ u64 ffma2(u64 a, u64 b, u64 c) {
    u64 d;
    asm("fma.rn.f32x2 %0, %1, %2, %3;" : "=l"(d) : "l"(a), "l"(b), "l"(c));
    return d;
}
__device__ __forceinline__ u64 fadd2(u64 a, u64 b) {
    u64 d;
    asm("add.rn.f32x2 %0, %1, %2;" : "=l"(d) : "l"(a), "l"(b));
    return d;
}
__device__ __forceinline__ void unpk2(float& lo, float& hi, u64 v) {
    asm("mov.b64 {%0,%1}, %2;" : "=f"(lo), "=f"(hi) : "l"(v));
}

// tf32 helpers
__device__ __forceinline__ uint32_t tf32_of(float x) {
    uint32_t r;
    asm("cvt.rna.tf32.f32 %0, %1;" : "=r"(r) : "f"(x));
    return r;
}
__device__ __forceinline__ void split_tf32(float x, uint32_t& hi, uint32_t& lo) {
    hi = tf32_of(x);
    float hif = __uint_as_float(hi);
    lo = tf32_of(x - hif);
}
__device__ __forceinline__ void mma_tf32(float* c, const uint32_t* a,
                                         uint32_t b0, uint32_t b1) {
    asm("mma.sync.aligned.m16n8k8.row.col.f32.tf32.tf32.f32 "
        "{%0,%1,%2,%3}, {%4,%5,%6,%7}, {%8,%9}, {%0,%1,%2,%3};"
        : "+f"(c[0]), "+f"(c[1]), "+f"(c[2]), "+f"(c[3])
        : "r"(a[0]), "r"(a[1]), "r"(a[2]), "r"(a[3]), "r"(b0), "r"(b1));
}

extern __shared__ float dynsm[];

// ---------------------------------------------------------------------------
// Kernel 1: input-projection GEMM on tensor cores (tf32 3-term split) + prep.
// W pre-split ONCE into paired (hi,lo) uint2 in smem (one LDS.64 fetches both
// terms); A stays float, split in-loop (only 2x redundancy).
// Per warp-ks: 12 LDS instr + 12 ALU (was 36) + 12 HMMA. smem 80.6KB.
// grid = (5, 32, 4): x in [0,4) -> 64-wide N tiles; x==4,y==0,z==0 -> prep.
// z = 0,1,2 -> mod0 K-chunk z; z = 3 -> mod1. 64m x 64n tile, 8 warps 4m x 2n.
// ---------------------------------------------------------------------------
__global__ void __launch_bounds__(256) gemm_xproj(
    const float* __restrict__ x0, const float* __restrict__ Wih0,
    const float* __restrict__ bih0, const float* __restrict__ bhh0,
    const float* __restrict__ x1, const float* __restrict__ Wih1,
    const float* __restrict__ bih1, const float* __restrict__ bhh1,
    const float* __restrict__ umask, const float* __restrict__ mk,
    const float* __restrict__ phase_tab) {

    if (blockIdx.x == 4) {
        if (blockIdx.y != 0 || blockIdx.z != 0) return;
        __shared__ float inv_norm[Uu];
        int tid = threadIdx.x;
        if (tid < Uu) {
            float s = 0.f;
            const float* p = mk + tid * (Ee * 2);
            #pragma unroll 8
            for (int i = 0; i < Ee * 2; i++) s += p[i] * p[i];
            inv_norm[tid] = 1.f / fmaxf(sqrtf(s), 1e-12f);
        }
        __syncthreads();
        for (int idx = tid; idx < Uu * Ee; idx += blockDim.x) {
            int u = idx >> 6;
            int e = idx & 63;
            float inv = inv_norm[u];
            g_krki[e * Uu + u] = make_float2(mk[(u * Ee + e) * 2 + 0] * inv,
                                             mk[(u * Ee + e) * 2 + 1] * inv);
        }
        for (int idx = tid; idx < Ss * Ee; idx += blockDim.x) {
            float p = phase_tab[idx];
            float s, c;
            sincosf(p, &s, &c);
            g_ph2[idx] = make_float2(c, s);
        }
        return;
    }

    int z = blockIdx.z;
    bool mod1 = (z == 3);
    const float* A   = mod1 ? x1 : x0;
    const float* W   = mod1 ? Wih1 : Wih0;
    const float* bih = mod1 ? bih1 : bih0;
    const float* bhh = mod1 ? bhh1 : bhh0;
    float* out = (z == 0) ? g_xp0a : (z == 1) ? g_xp0b : (z == 2) ? g_xp0c : g_xp1;
    const int Ks = mod1 ? D1 : D0;
    const int k0 = mod1 ? 0 : z * KC;
    const bool addb = (z == 0) || mod1;

    // Wsp first (uint2, 8B-aligned base), then As (float)
    uint2* Wsp = (uint2*)dynsm;             // [64][KSTR] (hi,lo) pairs
    float* As  = dynsm + 2 * 64 * KSTR;     // [64][KSTR]

    int tid = threadIdx.x;
    int bm = blockIdx.y * 64, bn = blockIdx.x * 64;

    // one-shot tile load; W split ONCE here, A stored raw
    for (int idx = tid; idx < 64 * KP; idx += 256) {
        int r = idx / KP;
        int k = idx - r * KP;
        bool v = k < KC;
        float a = v ? A[(size_t)(bm + r) * Ks + k0 + k] : 0.f;
        float w = v ? W[(size_t)(bn + r) * Ks + k0 + k] : 0.f;
        As[r * KSTR + k] = a;
        uint32_t h, l;
        split_tf32(w, h, l);
        Wsp[r * KSTR + k] = make_uint2(h, l);
    }
    __syncthreads();

    int warp = tid >> 5, lane = tid & 31;
    int wm = warp & 3;        // m offset wm*16
    int wn = warp >> 2;       // n offset wn*32
    int g = lane >> 2;        // 0..7
    int tg = lane & 3;        // 0..3

    float acc[4][4];
    #pragma unroll
    for (int nt = 0; nt < 4; nt++)
        #pragma unroll
        for (int i = 0; i < 4; i++) acc[nt][i] = 0.f;

    const float* Ar0 = As + (wm * 16 + g) * KSTR;
    const float* Ar8 = Ar0 + 8 * KSTR;

    #pragma unroll 1
    for (int ks = 0; ks < KP / 8; ks++) {
        int kk = ks * 8;
        float af0 = Ar0[kk + tg];
        float af1 = Ar8[kk + tg];
        float af2 = Ar0[kk + tg + 4];
        float af3 = Ar8[kk + tg + 4];
        uint32_t ah[4], al[4];
        split_tf32(af0, ah[0], al[0]);
        split_tf32(af1, ah[1], al[1]);
        split_tf32(af2, ah[2], al[2]);
        split_tf32(af3, ah[3], al[3]);

        #pragma unroll
        for (int nt = 0; nt < 4; nt++) {
            int wr = (wn * 32 + nt * 8 + g) * KSTR;
            uint2 p0 = Wsp[wr + kk + tg];       // (bh0, bl0) — one LDS.64
            uint2 p1 = Wsp[wr + kk + tg + 4];   // (bh1, bl1)
            mma_tf32(acc[nt], ah, p0.x, p1.x);  // hi*hi
            mma_tf32(acc[nt], ah, p0.y, p1.y);  // hi*lo
            mma_tf32(acc[nt], al, p0.x, p1.x);  // lo*hi
        }
    }

    // epilogue: D(m=g,+8 ; n=tg*2,+1) per n-tile
    int m0 = bm + wm * 16 + g;
    int m1 = m0 + 8;
    float um0 = umask[m0], um1 = umask[m1];
    #pragma unroll
    for (int nt = 0; nt < 4; nt++) {
        int n = bn + wn * 32 + nt * 8 + tg * 2;
        float bvx = 0.f, bvy = 0.f;
        if (addb) {
            bvx = bih[n + 0] + bhh[n + 0];
            bvy = bih[n + 1] + bhh[n + 1];
        }
        float2 o0, o1;
        o0.x = um0 * acc[nt][0] + bvx;
        o0.y = um0 * acc[nt][1] + bvy;
        o1.x = um1 * acc[nt][2] + bvx;
        o1.y = um1 * acc[nt][3] + bvy;
        *(float2*)&out[(size_t)m0 * G4E + n] = o0;
        *(float2*)&out[(size_t)m1 * G4E + n] = o1;
    }
}

// ---------------------------------------------------------------------------
// Kernel 1.5: reduce mod0 chunk partials into g_xp0a (float4, elementwise).
// ---------------------------------------------------------------------------
__global__ void __launch_bounds__(256) reduce_xp0() {
    int i = blockIdx.x * blockDim.x + threadIdx.x;
    float4 a = ((const float4*)g_xp0a)[i];
    float4 b = ((const float4*)g_xp0b)[i];
    float4 c = ((const float4*)g_xp0c)[i];
    a.x += b.x + c.x;
    a.y += b.y + c.y;
    a.z += b.z + c.z;
    a.w += b.w + c.w;
    ((float4*)g_xp0a)[i] = a;
}

// ---------------------------------------------------------------------------
// Kernel 2: LSTM recurrence — single xp stream, depth-1 prefetch, shuffle
// gather, double-buffered h, one barrier per step, MUFU.TANH. (R13 config.)
// ---------------------------------------------------------------------------
__global__ void __launch_bounds__(256, 1) lstm_kernel(
    const float* __restrict__ Whh0, const float* __restrict__ Whh1) {
    int mod = blockIdx.x >> 5;
    int b = blockIdx.x & 31;
    const float* Whh = mod ? Whh1 : Whh0;
    const float* xp = (mod ? g_xp1 : g_xp0a) + (size_t)b * Tt * G4E;
    float* hout = (mod ? g_h1 : g_h0) + (size_t)b * Tt * Ee;

    int tid = threadIdx.x;
    int w = tid >> 5, l = tid & 31;
    int gt = l & 3;
    int cell = w * 8 + (l >> 2);
    int r = gt * 64 + cell;

    u64 wp[32];
    {
        const float2* src = (const float2*)(Whh + (size_t)r * Ee);
        #pragma unroll
        for (int i = 0; i < 32; i++) {
            union { float2 f; u64 u; } cv;
            cv.f = src[i];
            wp[i] = cv.u;
        }
    }

    __shared__ __align__(16) float hs[2][Ee];
    if (tid < Ee) hs[0][tid] = 0.f;
    float c = 0.f;
    __syncthreads();

    float gpre = xp[r];
    #pragma unroll 1
    for (int t = 0; t < Tt; t++) {
        float gnext = (t + 1 < Tt) ? xp[(t + 1) * G4E + r] : 0.f;  // prefetch

        const ulonglong2* h2 = (const ulonglong2*)hs[t & 1];
        u64 a0 = 0ull, a1 = 0ull, a2 = 0ull, a3 = 0ull;
        #pragma unroll
        for (int i = 0; i < 16; i += 2) {
            ulonglong2 hv = h2[i];
            a0 = ffma2(wp[2 * i + 0], hv.x, a0);
            a1 = ffma2(wp[2 * i + 1], hv.y, a1);
            ulonglong2 hv2 = h2[i + 1];
            a2 = ffma2(wp[2 * i + 2], hv2.x, a2);
            a3 = ffma2(wp[2 * i + 3], hv2.y, a3);
        }
        u64 s = fadd2(fadd2(a0, a1), fadd2(a2, a3));
        float lo, hi;
        unpk2(lo, hi, s);
        float g = gpre + lo + hi;
        gpre = gnext;

        float act = (gt == 2) ? tanha(g) : fsig(g);

        float v1 = __shfl_xor_sync(0xffffffffu, act, 1);
        float v2 = __shfl_xor_sync(0xffffffffu, act, 2);
        float v3 = __shfl_xor_sync(0xffffffffu, act, 3);

        if (gt == 0) {
            // act=sig(i), v1=sig(f), v2=tanh(g), v3=sig(o)
            c = v1 * c + act * v2;
            float h = tanha(v3 * tanha(c));
            hs[(t + 1) & 1][cell] = h;
            hout[t * Ee + cell] = h;
        }
        __syncthreads();
    }
}

// ---------------------------------------------------------------------------
// Kernel 3: warp-per-row epilogue, 16 rows/block (512 thr), h prefetched
// before the staging barrier, MUFU tail. (R13 config.)
// ---------------------------------------------------------------------------
__global__ void __launch_bounds__(512) epilogue_kernel(
    const float* __restrict__ smask,
    const float* __restrict__ W1, const float* __restrict__ b1,
    const float* __restrict__ W2, const float* __restrict__ b2,
    float* __restrict__ out) {
    __shared__ __align__(16) float2 krki[Ee * Uu];
    __shared__ __align__(16) float2 ph2s[Ss * Ee];
    __shared__ float W1s[CELL * 65];
    __shared__ float W2s[Cc * 65];
    __shared__ __align__(16) float4 riS[EPW][Ee];
    __shared__ float msS[EPW][2 * Uu];
    __shared__ float hidS[EPW][CELL];

    int tid = threadIdx.x;
    int wid = tid >> 5;
    int lane = tid & 31;
    int row = blockIdx.x * EPW + wid;

    const float* h0p = g_h0 + (size_t)row * Ee;
    const float* h1p = g_h1 + (size_t)row * Ee;
    float h0a = h0p[lane], h0b = h0p[lane + 32];
    float h1a = h1p[lane], h1b = h1p[lane + 32];
    float av = (lane < Ss) ? smask[row * Ss + lane] : -1e30f;

    for (int i = tid; i < (Ee * Uu) / 2; i += 512)
        ((float4*)krki)[i] = ((const float4*)g_krki)[i];
    for (int i = tid; i < (Ss * Ee) / 2; i += 512)
        ((float4*)ph2s)[i] = ((const float4*)g_ph2)[i];
    for (int i = tid; i < CELL * CELL; i += 512)
        W1s[(i >> 6) * 65 + (i & 63)] = W1[i];
    for (int i = tid; i < Cc * CELL; i += 512)
        W2s[(i >> 6) * 65 + (i & 63)] = W2[i];
    __syncthreads();

    float v0 = h0a * h0a + h0b * h0b;
    float v1 = h1a * h1a + h1b * h1b;
    int ai = lane;
    #pragma unroll
    for (int off = 16; off; off >>= 1) {
        v0 += __shfl_xor_sync(0xffffffffu, v0, off);
        v1 += __shfl_xor_sync(0xffffffffu, v1, off);
        float ov = __shfl_xor_sync(0xffffffffu, av, off);
        int oi = __shfl_xor_sync(0xffffffffu, ai, off);
        if (ov > av || (ov == av && oi < ai)) { av = ov; ai = oi; }
    }
    float inv0 = rsqrtf(fmaxf(v0, 1e-24f));
    float inv1 = rsqrtf(fmaxf(v1, 1e-24f));
    int sidx = ai;

    float2 pa = ph2s[sidx * Ee + lane];
    float2 pb = ph2s[sidx * Ee + lane + 32];
    float n0a = h0a * inv0, n0b = h0b * inv0;
    float n1a = h1a * inv1, n1b = h1b * inv1;
    riS[wid][lane]      = make_float4(pa.x * n0a, pa.y * n0a, pa.x * n1a, pa.y * n1a);
    riS[wid][lane + 32] = make_float4(pb.x * n0b, pb.y * n0b, pb.x * n1b, pb.y * n1b);
    __syncwarp();

    {
        float pr0 = 0.f, pi0 = 0.f, pr1 = 0.f, pi1 = 0.f;
        #pragma unroll 8
        for (int e = 0; e < Ee; e++) {
            float4 ri = riS[wid][e];
            float2 kk = krki[e * Uu + lane];
            pr0 += kk.x * ri.x - kk.y * ri.y;
            pi0 += kk.y * ri.x + kk.x * ri.y;
            pr1 += kk.x * ri.z - kk.y * ri.w;
            pi1 += kk.y * ri.z + kk.x * ri.w;
        }
        msS[wid][lane]      = pr0 * pr0 + pi0 * pi0;
        msS[wid][lane + 32] = pr1 * pr1 + pi1 * pi1;
    }
    __syncwarp();

    {
        float acc0 = b1[lane], acc1 = b1[lane + 32];
        const float* w1a = &W1s[lane * 65];
        const float* w1b = &W1s[(lane + 32) * 65];
        #pragma unroll 8
        for (int k = 0; k < CELL; k++) {
            float mv = msS[wid][k];
            acc0 += mv * w1a[k];
            acc1 += mv * w1b[k];
        }
        hidS[wid][lane]      = fmaxf(acc0, 0.f);
        hidS[wid][lane + 32] = fmaxf(acc1, 0.f);
    }
    __syncwarp();

    float pred = 0.f;
    if (lane < Cc) {
        float a = b2[lane];
        const float* w2 = &W2s[lane * 65];
        #pragma unroll 8
        for (int k = 0; k < CELL; k++) a += hidS[wid][k] * w2[k];
        pred = tanha(a);
    }
    float p0 = __shfl_sync(0xffffffffu, pred, 0);
    float p1 = __shfl_sync(0xffffffffu, pred, 1);
    float p2 = __shfl_sync(0xffffffffu, pred, 2);
    float p3 = __shfl_sync(0xffffffffu, pred, 3);
    float p4 = __shfl_sync(0xffffffffu, pred, 4);
    float p5 = __shfl_sync(0xffffffffu, pred, 5);
    if (lane < Cc) {
        float m = fmaxf(fmaxf(fmaxf(p0, p1), fmaxf(p2, p3)), fmaxf(p4, p5));
        float se = __expf(p0 - m) + __expf(p1 - m) + __expf(p2 - m)
                 + __expf(p3 - m) + __expf(p4 - m) + __expf(p5 - m);
        out[row * Cc + lane] = pred - (m + __logf(se));
    }
}

// ---------------------------------------------------------------------------
extern "C" void kernel_launch(void* const* d_in, const int* in_sizes, int n_in,
                              void* d_out, int out_size) {
    const float* x0        = (const float*)d_in[0];
    const float* x1        = (const float*)d_in[1];
    const float* smask     = (const float*)d_in[2];
    const float* umask     = (const float*)d_in[3];
    const float* W_ih0     = (const float*)d_in[4];
    const float* W_hh0     = (const float*)d_in[5];
    const float* b_ih0     = (const float*)d_in[6];
    const float* b_hh0     = (const float*)d_in[7];
    const float* W_ih1     = (const float*)d_in[8];
    const float* W_hh1     = (const float*)d_in[9];
    const float* b_ih1     = (const float*)d_in[10];
    const float* b_hh1     = (const float*)d_in[11];
    const float* phase_tab = (const float*)d_in[12];
    const float* meas_k    = (const float*)d_in[13];
    const float* W1        = (const float*)d_in[14];
    const float* b1        = (const float*)d_in[15];
    const float* W2        = (const float*)d_in[16];
    const float* b2        = (const float*)d_in[17];
    float* out = (float*)d_out;

    const int smem_gemm = 3 * 64 * KSTR * sizeof(float);   // 80640 B
    cudaFuncSetAttribute(gemm_xproj,
                         cudaFuncAttributeMaxDynamicSharedMemorySize, smem_gemm);

    dim3 ggrid(5, ROWS / 64, 4);   // (5, 32, 4): 3 mod0 chunks + mod1 + prep
    gemm_xproj<<<ggrid, 256, smem_gemm>>>(x0, W_ih0, b_ih0, b_hh0,
                                          x1, W_ih1, b_ih1, b_hh1,
                                          umask, meas_k, phase_tab);

    reduce_xp0<<<ROWS * G4E / 4 / 256, 256>>>();

    lstm_kernel<<<64, 256>>>(W_hh0, W_hh1);

    epilogue_kernel<<<ROWS / EPW, 512>>>(smask, W1, b1, W2, b2, out);
}

// round 17
// speedup vs baseline: 1.1159x; 1.1159x over previous
#include <cuda_runtime.h>
#include <math.h>
#include <stdint.h>

// Problem constants
#define Bb 32
#define Tt 64
#define Ee 64
#define Uu 32
#define D0 300
#define D1 100
#define Ss 9
#define CELL 64
#define Cc 6
#define ROWS (Bb*Tt)      // 2048
#define G4E (4*Ee)        // 256
#define KC 100            // uniform K-chunk
#define KP 104            // K padded to multiple of 8
#define KSTR 105          // smem row stride (floats)
#define EPW 16            // epilogue rows (warps) per block

// Device scratch
__device__ float g_xp0a[ROWS * G4E];
__device__ float g_xp0b[ROWS * G4E];
__device__ float g_xp0c[ROWS * G4E];
__device__ float g_xp1 [ROWS * G4E];
__device__ float g_h0[ROWS * Ee];
__device__ float g_h1[ROWS * Ee];
__device__ float2 g_krki[Ee * Uu];   // [e][u] -> (kr, ki), normalized
__device__ float2 g_ph2[Ss * Ee];    // [s][e] -> (cos, sin)

typedef unsigned long long u64;

// ---------------------------------------------------------------------------
__device__ __forceinline__ float tanha(float x) {
    float y;
    asm("tanh.approx.f32 %0, %1;" : "=f"(y) : "f"(x));
    return y;
}
__device__ __forceinline__ float fsig(float x) {
    return fmaf(tanha(0.5f * x), 0.5f, 0.5f);
}
__device__ __forceinline__ u64 ffma2(u64 a, u64 b, u64 c) {
    u64 d;
    asm("fma.rn.f32x2 %0, %1, %2, %3;" : "=l"(d) : "l"(a), "l"(b), "l"(c));
    return d;
}
__device__ __forceinline__ u64 fadd2(u64 a, u64 b) {
    u64 d;
    asm("add.rn.f32x2 %0, %1, %2;" : "=l"(d) : "l"(a), "l"(b));
    return d;
}
__device__ __forceinline__ void unpk2(float& lo, float& hi, u64 v) {
    asm("mov.b64 {%0,%1}, %2;" : "=f"(lo), "=f"(hi) : "l"(v));
}

// tf32 helpers — MASK-BASED split: hi = x & 0xFFFFE000 (exact tf32 via LOP3),
// lo = x - hi (exact fp32; MMA HW ignores low 13 mantissa bits on read).
// 2 cheap ALU ops per split instead of 2x cvt(20cyc) + fsub.
__device__ __forceinline__ void split_tf32(float x, uint32_t& hi, uint32_t& lo) {
    hi = __float_as_uint(x) & 0xFFFFE000u;
    lo = __float_as_uint(x - __uint_as_float(hi));
}
__device__ __forceinline__ void mma_tf32(float* c, const uint32_t* a,
                                         uint32_t b0, uint32_t b1) {
    asm("mma.sync.aligned.m16n8k8.row.col.f32.tf32.tf32.f32 "
        "{%0,%1,%2,%3}, {%4,%5,%6,%7}, {%8,%9}, {%0,%1,%2,%3};"
        : "+f"(c[0]), "+f"(c[1]), "+f"(c[2]), "+f"(c[3])
        : "r"(a[0]), "r"(a[1]), "r"(a[2]), "r"(a[3]), "r"(b0), "r"(b1));
}

extern __shared__ float dynsm[];

// ---------------------------------------------------------------------------
// Kernel 1: input-projection GEMM on tensor cores (tf32 3-term split) + prep.
// R13 layout verbatim (measured best); only the split op is cheaper now.
// grid = (5, 32, 4): x in [0,4) -> 64-wide N tiles; x==4,y==0,z==0 -> prep.
// z = 0,1,2 -> mod0 K-chunk z; z = 3 -> mod1. 64m x 64n tile, 8 warps 4m x 2n.
// ---------------------------------------------------------------------------
__global__ void __launch_bounds__(256) gemm_xproj(
    const float* __restrict__ x0, const float* __restrict__ Wih0,
    const float* __restrict__ bih0, const float* __restrict__ bhh0,
    const float* __restrict__ x1, const float* __restrict__ Wih1,
    const float* __restrict__ bih1, const float* __restrict__ bhh1,
    const float* __restrict__ umask, const float* __restrict__ mk,
    const float* __restrict__ phase_tab) {

    if (blockIdx.x == 4) {
        if (blockIdx.y != 0 || blockIdx.z != 0) return;
        __shared__ float inv_norm[Uu];
        int tid = threadIdx.x;
        if (tid < Uu) {
            float s = 0.f;
            const float* p = mk + tid * (Ee * 2);
            #pragma unroll 8
            for (int i = 0; i < Ee * 2; i++) s += p[i] * p[i];
            inv_norm[tid] = 1.f / fmaxf(sqrtf(s), 1e-12f);
        }
        __syncthreads();
        for (int idx = tid; idx < Uu * Ee; idx += blockDim.x) {
            int u = idx >> 6;
            int e = idx & 63;
            float inv = inv_norm[u];
            g_krki[e * Uu + u] = make_float2(mk[(u * Ee + e) * 2 + 0] * inv,
                                             mk[(u * Ee + e) * 2 + 1] * inv);
        }
        for (int idx = tid; idx < Ss * Ee; idx += blockDim.x) {
            float p = phase_tab[idx];
            float s, c;
            sincosf(p, &s, &c);
            g_ph2[idx] = make_float2(c, s);
        }
        return;
    }

    int z = blockIdx.z;
    bool mod1 = (z == 3);
    const float* A   = mod1 ? x1 : x0;
    const float* W   = mod1 ? Wih1 : Wih0;
    const float* bih = mod1 ? bih1 : bih0;
    const float* bhh = mod1 ? bhh1 : bhh0;
    float* out = (z == 0) ? g_xp0a : (z == 1) ? g_xp0b : (z == 2) ? g_xp0c : g_xp1;
    const int Ks = mod1 ? D1 : D0;
    const int k0 = mod1 ? 0 : z * KC;
    const bool addb = (z == 0) || mod1;

    float* As  = dynsm;
    float* Wsm = dynsm + 64 * KSTR;

    int tid = threadIdx.x;
    int bm = blockIdx.y * 64, bn = blockIdx.x * 64;

    // one-shot tile load (zero-pad k in [KC, KP))
    for (int idx = tid; idx < 64 * KP; idx += 256) {
        int r = idx / KP;
        int k = idx - r * KP;
        bool v = k < KC;
        As [r * KSTR + k] = v ? A[(size_t)(bm + r) * Ks + k0 + k] : 0.f;
        Wsm[r * KSTR + k] = v ? W[(size_t)(bn + r) * Ks + k0 + k] : 0.f;
    }
    __syncthreads();

    int warp = tid >> 5, lane = tid & 31;
    int wm = warp & 3;
    int wn = warp >> 2;
    int g = lane >> 2;
    int tg = lane & 3;

    float acc[4][4];
    #pragma unroll
    for (int nt = 0; nt < 4; nt++)
        #pragma unroll
        for (int i = 0; i < 4; i++) acc[nt][i] = 0.f;

    const float* Ar0 = As + (wm * 16 + g) * KSTR;
    const float* Ar8 = Ar0 + 8 * KSTR;

    #pragma unroll 1
    for (int ks = 0; ks < KP / 8; ks++) {
        int kk = ks * 8;
        float af0 = Ar0[kk + tg];
        float af1 = Ar8[kk + tg];
        float af2 = Ar0[kk + tg + 4];
        float af3 = Ar8[kk + tg + 4];
        uint32_t ah[4], al[4];
        split_tf32(af0, ah[0], al[0]);
        split_tf32(af1, ah[1], al[1]);
        split_tf32(af2, ah[2], al[2]);
        split_tf32(af3, ah[3], al[3]);

        #pragma unroll
        for (int nt = 0; nt < 4; nt++) {
            const float* Wr = Wsm + (wn * 32 + nt * 8 + g) * KSTR;
            float bf0 = Wr[kk + tg];
            float bf1 = Wr[kk + tg + 4];
            uint32_t bh0, bl0, bh1, bl1;
            split_tf32(bf0, bh0, bl0);
            split_tf32(bf1, bh1, bl1);
            mma_tf32(acc[nt], ah, bh0, bh1);   // hi*hi
            mma_tf32(acc[nt], ah, bl0, bl1);   // hi*lo
            mma_tf32(acc[nt], al, bh0, bh1);   // lo*hi
        }
    }

    // epilogue: D(m=g,+8 ; n=tg*2,+1) per n-tile
    int m0 = bm + wm * 16 + g;
    int m1 = m0 + 8;
    float um0 = umask[m0], um1 = umask[m1];
    #pragma unroll
    for (int nt = 0; nt < 4; nt++) {
        int n = bn + wn * 32 + nt * 8 + tg * 2;
        float bvx = 0.f, bvy = 0.f;
        if (addb) {
            bvx = bih[n + 0] + bhh[n + 0];
            bvy = bih[n + 1] + bhh[n + 1];
        }
        float2 o0, o1;
        o0.x = um0 * acc[nt][0] + bvx;
        o0.y = um0 * acc[nt][1] + bvy;
        o1.x = um1 * acc[nt][2] + bvx;
        o1.y = um1 * acc[nt][3] + bvy;
        *(float2*)&out[(size_t)m0 * G4E + n] = o0;
        *(float2*)&out[(size_t)m1 * G4E + n] = o1;
    }
}

// ---------------------------------------------------------------------------
// Kernel 1.5: reduce mod0 chunk partials into g_xp0a (float4, elementwise).
// ---------------------------------------------------------------------------
__global__ void __launch_bounds__(256) reduce_xp0() {
    int i = blockIdx.x * blockDim.x + threadIdx.x;
    float4 a = ((const float4*)g_xp0a)[i];
    float4 b = ((const float4*)g_xp0b)[i];
    float4 c = ((const float4*)g_xp0c)[i];
    a.x += b.x + c.x;
    a.y += b.y + c.y;
    a.z += b.z + c.z;
    a.w += b.w + c.w;
    ((float4*)g_xp0a)[i] = a;
}

// ---------------------------------------------------------------------------
// Kernel 2: LSTM recurrence — single xp stream, depth-1 prefetch, shuffle
// gather, double-buffered h, one barrier per step, MUFU.TANH. (R13 config.)
// ---------------------------------------------------------------------------
__global__ void __launch_bounds__(256, 1) lstm_kernel(
    const float* __restrict__ Whh0, const float* __restrict__ Whh1) {
    int mod = blockIdx.x >> 5;
    int b = blockIdx.x & 31;
    const float* Whh = mod ? Whh1 : Whh0;
    const float* xp = (mod ? g_xp1 : g_xp0a) + (size_t)b * Tt * G4E;
    float* hout = (mod ? g_h1 : g_h0) + (size_t)b * Tt * Ee;

    int tid = threadIdx.x;
    int w = tid >> 5, l = tid & 31;
    int gt = l & 3;
    int cell = w * 8 + (l >> 2);
    int r = gt * 64 + cell;

    u64 wp[32];
    {
        const float2* src = (const float2*)(Whh + (size_t)r * Ee);
        #pragma unroll
        for (int i = 0; i < 32; i++) {
            union { float2 f; u64 u; } cv;
            cv.f = src[i];
            wp[i] = cv.u;
        }
    }

    __shared__ __align__(16) float hs[2][Ee];
    if (tid < Ee) hs[0][tid] = 0.f;
    float c = 0.f;
    __syncthreads();

    float gpre = xp[r];
    #pragma unroll 1
    for (int t = 0; t < Tt; t++) {
        float gnext = (t + 1 < Tt) ? xp[(t + 1) * G4E + r] : 0.f;  // prefetch

        const ulonglong2* h2 = (const ulonglong2*)hs[t & 1];
        u64 a0 = 0ull, a1 = 0ull, a2 = 0ull, a3 = 0ull;
        #pragma unroll
        for (int i = 0; i < 16; i += 2) {
            ulonglong2 hv = h2[i];
            a0 = ffma2(wp[2 * i + 0], hv.x, a0);
            a1 = ffma2(wp[2 * i + 1], hv.y, a1);
            ulonglong2 hv2 = h2[i + 1];
            a2 = ffma2(wp[2 * i + 2], hv2.x, a2);
            a3 = ffma2(wp[2 * i + 3], hv2.y, a3);
        }
        u64 s = fadd2(fadd2(a0, a1), fadd2(a2, a3));
        float lo, hi;
        unpk2(lo, hi, s);
        float g = gpre + lo + hi;
        gpre = gnext;

        float act = (gt == 2) ? tanha(g) : fsig(g);

        float v1 = __shfl_xor_sync(0xffffffffu, act, 1);
        float v2 = __shfl_xor_sync(0xffffffffu, act, 2);
        float v3 = __shfl_xor_sync(0xffffffffu, act, 3);

        if (gt == 0) {
            // act=sig(i), v1=sig(f), v2=tanh(g), v3=sig(o)
            c = v1 * c + act * v2;
            float h = tanha(v3 * tanha(c));
            hs[(t + 1) & 1][cell] = h;
            hout[t * Ee + cell] = h;
        }
        __syncthreads();
    }
}

// ---------------------------------------------------------------------------
// Kernel 3: warp-per-row epilogue, 16 rows/block (512 thr), h prefetched
// before the staging barrier, MUFU tail. (R13 config.)
// ---------------------------------------------------------------------------
__global__ void __launch_bounds__(512) epilogue_kernel(
    const float* __restrict__ smask,
    const float* __restrict__ W1, const float* __restrict__ b1,
    const float* __restrict__ W2, const float* __restrict__ b2,
    float* __restrict__ out) {
    __shared__ __align__(16) float2 krki[Ee * Uu];
    __shared__ __align__(16) float2 ph2s[Ss * Ee];
    __shared__ float W1s[CELL * 65];
    __shared__ float W2s[Cc * 65];
    __shared__ __align__(16) float4 riS[EPW][Ee];
    __shared__ float msS[EPW][2 * Uu];
    __shared__ float hidS[EPW][CELL];

    int tid = threadIdx.x;
    int wid = tid >> 5;
    int lane = tid & 31;
    int row = blockIdx.x * EPW + wid;

    const float* h0p = g_h0 + (size_t)row * Ee;
    const float* h1p = g_h1 + (size_t)row * Ee;
    float h0a = h0p[lane], h0b = h0p[lane + 32];
    float h1a = h1p[lane], h1b = h1p[lane + 32];
    float av = (lane < Ss) ? smask[row * Ss + lane] : -1e30f;

    for (int i = tid; i < (Ee * Uu) / 2; i += 512)
        ((float4*)krki)[i] = ((const float4*)g_krki)[i];
    for (int i = tid; i < (Ss * Ee) / 2; i += 512)
        ((float4*)ph2s)[i] = ((const float4*)g_ph2)[i];
    for (int i = tid; i < CELL * CELL; i += 512)
        W1s[(i >> 6) * 65 + (i & 63)] = W1[i];
    for (int i = tid; i < Cc * CELL; i += 512)
        W2s[(i >> 6) * 65 + (i & 63)] = W2[i];
    __syncthreads();

    float v0 = h0a * h0a + h0b * h0b;
    float v1 = h1a * h1a + h1b * h1b;
    int ai = lane;
    #pragma unroll
    for (int off = 16; off; off >>= 1) {
        v0 += __shfl_xor_sync(0xffffffffu, v0, off);
        v1 += __shfl_xor_sync(0xffffffffu, v1, off);
        float ov = __shfl_xor_sync(0xffffffffu, av, off);
        int oi = __shfl_xor_sync(0xffffffffu, ai, off);
        if (ov > av || (ov == av && oi < ai)) { av = ov; ai = oi; }
    }
    float inv0 = rsqrtf(fmaxf(v0, 1e-24f));
    float inv1 = rsqrtf(fmaxf(v1, 1e-24f));
    int sidx = ai;

    float2 pa = ph2s[sidx * Ee + lane];
    float2 pb = ph2s[sidx * Ee + lane + 32];
    float n0a = h0a * inv0, n0b = h0b * inv0;
    float n1a = h1a * inv1, n1b = h1b * inv1;
    riS[wid][lane]      = make_float4(pa.x * n0a, pa.y * n0a, pa.x * n1a, pa.y * n1a);
    riS[wid][lane + 32] = make_float4(pb.x * n0b, pb.y * n0b, pb.x * n1b, pb.y * n1b);
    __syncwarp();

    {
        float pr0 = 0.f, pi0 = 0.f, pr1 = 0.f, pi1 = 0.f;
        #pragma unroll 8
        for (int e = 0; e < Ee; e++) {
            float4 ri = riS[wid][e];
            float2 kk = krki[e * Uu + lane];
            pr0 += kk.x * ri.x - kk.y * ri.y;
            pi0 += kk.y * ri.x + kk.x * ri.y;
            pr1 += kk.x * ri.z - kk.y * ri.w;
            pi1 += kk.y * ri.z + kk.x * ri.w;
        }
        msS[wid][lane]      = pr0 * pr0 + pi0 * pi0;
        msS[wid][lane + 32] = pr1 * pr1 + pi1 * pi1;
    }
    __syncwarp();

    {
        float acc0 = b1[lane], acc1 = b1[lane + 32];
        const float* w1a = &W1s[lane * 65];
        const float* w1b = &W1s[(lane + 32) * 65];
        #pragma unroll 8
        for (int k = 0; k < CELL; k++) {
            float mv = msS[wid][k];
            acc0 += mv * w1a[k];
            acc1 += mv * w1b[k];
        }
        hidS[wid][lane]      = fmaxf(acc0, 0.f);
        hidS[wid][lane + 32] = fmaxf(acc1, 0.f);
    }
    __syncwarp();

    float pred = 0.f;
    if (lane < Cc) {
        float a = b2[lane];
        const float* w2 = &W2s[lane * 65];
        #pragma unroll 8
        for (int k = 0; k < CELL; k++) a += hidS[wid][k] * w2[k];
        pred = tanha(a);
    }
    float p0 = __shfl_sync(0xffffffffu, pred, 0);
    float p1 = __shfl_sync(0xffffffffu, pred, 1);
    float p2 = __shfl_sync(0xffffffffu, pred, 2);
    float p3 = __shfl_sync(0xffffffffu, pred, 3);
    float p4 = __shfl_sync(0xffffffffu, pred, 4);
    float p5 = __shfl_sync(0xffffffffu, pred, 5);
    if (lane < Cc) {
        float m = fmaxf(fmaxf(fmaxf(p0, p1), fmaxf(p2, p3)), fmaxf(p4, p5));
        float se = __expf(p0 - m) + __expf(p1 - m) + __expf(p2 - m)
                 + __expf(p3 - m) + __expf(p4 - m) + __expf(p5 - m);
        out[row * Cc + lane] = pred - (m + __logf(se));
    }
}

// ---------------------------------------------------------------------------
extern "C" void kernel_launch(void* const* d_in, const int* in_sizes, int n_in,
                              void* d_out, int out_size) {
    const float* x0        = (const float*)d_in[0];
    const float* x1        = (const float*)d_in[1];
    const float* smask     = (const float*)d_in[2];
    const float* umask     = (const float*)d_in[3];
    const float* W_ih0     = (const float*)d_in[4];
    const float* W_hh0     = (const float*)d_in[5];
    const float* b_ih0     = (const float*)d_in[6];
    const float* b_hh0     = (const float*)d_in[7];
    const float* W_ih1     = (const float*)d_in[8];
    const float* W_hh1     = (const float*)d_in[9];
    const float* b_ih1     = (const float*)d_in[10];
    const float* b_hh1     = (const float*)d_in[11];
    const float* phase_tab = (const float*)d_in[12];
    const float* meas_k    = (const float*)d_in[13];
    const float* W1        = (const float*)d_in[14];
    const float* b1        = (const float*)d_in[15];
    const float* W2        = (const float*)d_in[16];
    const float* b2        = (const float*)d_in[17];
    float* out = (float*)d_out;

    const int smem_gemm = 2 * 64 * KSTR * sizeof(float);   // 53760 B (R13)
    cudaFuncSetAttribute(gemm_xproj,
                         cudaFuncAttributeMaxDynamicSharedMemorySize, smem_gemm);

    dim3 ggrid(5, ROWS / 64, 4);   // (5, 32, 4): 3 mod0 chunks + mod1 + prep
    gemm_xproj<<<ggrid, 256, smem_gemm>>>(x0, W_ih0, b_ih0, b_hh0,
                                          x1, W_ih1, b_ih1, b_hh1,
                                          umask, meas_k, phase_tab);

    reduce_xp0<<<ROWS * G4E / 4 / 256, 256>>>();

    lstm_kernel<<<64, 256>>>(W_hh0, W_hh1);

    epilogue_kernel<<<ROWS / EPW, 512>>>(smask, W1, b1, W2, b2, out);
}